// round 3
// baseline (speedup 1.0000x reference)
#include <cuda_runtime.h>
#include <math.h>

// Problem shape (fixed by reference setup_inputs)
#define B_ 4
#define C_ 3
#define H_ 1024
#define W_ 1920
#define HW_ (H_ * W_)          // 1,966,080
#define NPIX_ (B_ * HW_)       // 7,864,320

// Scratch: splat weight-channel accumulator (em splatted). Static device array
// (no runtime allocation).
__device__ float g_weight[NPIX_];

// ---------------------------------------------------------------------------
// Kernel 1: zero the splat accumulator region of d_out (3*NPIX floats) and
// the weight buffer (NPIX floats). Vectorized float4 stores.
// 3*NPIX = 23,592,960 floats (divisible by 4); NPIX divisible by 4.
// ---------------------------------------------------------------------------
__global__ void zero_kernel(float4* __restrict__ out4) {
    const int n_out4 = (3 * NPIX_) / 4;   // 5,898,240
    const int n_w4   = NPIX_ / 4;         // 1,966,080
    int i = blockIdx.x * blockDim.x + threadIdx.x;
    float4 z = make_float4(0.f, 0.f, 0.f, 0.f);
    if (i < n_out4) out4[i] = z;
    if (i < n_w4)   reinterpret_cast<float4*>(g_weight)[i] = z;
}

// ---------------------------------------------------------------------------
// Kernel 2: per source pixel — backwarp rgb2, metric, exp weight, splat.
// ---------------------------------------------------------------------------
__global__ void __launch_bounds__(256)
softsplat_kernel(const float* __restrict__ rgb1,
                 const float* __restrict__ rgb2,
                 const float* __restrict__ flow_tgt,
                 const float* __restrict__ flow12,
                 float* __restrict__ out,        // [B,3,H,W] splat accumulator
                 float* __restrict__ metric_out) // [B,1,H,W]
{
    int i = blockIdx.x * blockDim.x + threadIdx.x;
    if (i >= NPIX_) return;

    const int b  = i / HW_;
    const int hw = i - b * HW_;
    const int h  = hw / W_;
    const int w  = hw - h * W_;

    // ---- backwarp rgb2 with flow_src1_to_src2 (bilinear, zero padding) ----
    const float* f12 = flow12 + (size_t)b * 2 * HW_;
    const float px = (float)w + f12[hw];
    const float py = (float)h + f12[HW_ + hw];
    const float x0f = floorf(px);
    const float y0f = floorf(py);
    const int   x0  = (int)x0f;
    const int   y0  = (int)y0f;
    const float wx  = px - x0f;
    const float wy  = py - y0f;

    const float* img2 = rgb2 + (size_t)b * 3 * HW_;
    float w00 = 0.f, w01 = 0.f, w02 = 0.f;  // warped channels

    {
        // corner (x0, y0)
        if (x0 >= 0 && x0 < W_ && y0 >= 0 && y0 < H_) {
            const float wt = (1.f - wx) * (1.f - wy);
            const int idx = y0 * W_ + x0;
            w00 += img2[idx] * wt;
            w01 += img2[HW_ + idx] * wt;
            w02 += img2[2 * HW_ + idx] * wt;
        }
        // corner (x0+1, y0)
        if (x0 + 1 >= 0 && x0 + 1 < W_ && y0 >= 0 && y0 < H_) {
            const float wt = wx * (1.f - wy);
            const int idx = y0 * W_ + x0 + 1;
            w00 += img2[idx] * wt;
            w01 += img2[HW_ + idx] * wt;
            w02 += img2[2 * HW_ + idx] * wt;
        }
        // corner (x0, y0+1)
        if (x0 >= 0 && x0 < W_ && y0 + 1 >= 0 && y0 + 1 < H_) {
            const float wt = (1.f - wx) * wy;
            const int idx = (y0 + 1) * W_ + x0;
            w00 += img2[idx] * wt;
            w01 += img2[HW_ + idx] * wt;
            w02 += img2[2 * HW_ + idx] * wt;
        }
        // corner (x0+1, y0+1)
        if (x0 + 1 >= 0 && x0 + 1 < W_ && y0 + 1 >= 0 && y0 + 1 < H_) {
            const float wt = wx * wy;
            const int idx = (y0 + 1) * W_ + x0 + 1;
            w00 += img2[idx] * wt;
            w01 += img2[HW_ + idx] * wt;
            w02 += img2[2 * HW_ + idx] * wt;
        }
    }

    // ---- metric = channel-mean L1(rgb1, backwarped) ----
    const float* img1 = rgb1 + (size_t)b * 3 * HW_;
    const float r0 = img1[hw];
    const float r1 = img1[HW_ + hw];
    const float r2 = img1[2 * HW_ + hw];

    const float metric = (fabsf(r0 - w00) + fabsf(r1 - w01) + fabsf(r2 - w02))
                         * (1.f / 3.f);
    metric_out[(size_t)b * HW_ + hw] = metric;

    // em = exp(clip(-100*metric, -100, 100)); metric >= 0 so upper clip moot
    const float em = expf(fmaxf(-100.f * metric, -100.f));

    // ---- forward splat of [r*em, em] with flow_src1_to_tgt ----
    const float* ftg = flow_tgt + (size_t)b * 2 * HW_;
    const float qx = (float)w + ftg[hw];
    const float qy = (float)h + ftg[HW_ + hw];
    const float qx0f = floorf(qx);
    const float qy0f = floorf(qy);
    const int   qx0  = (int)qx0f;
    const int   qy0  = (int)qy0f;
    const float ux   = qx - qx0f;
    const float uy   = qy - qy0f;

    const float v0 = r0 * em;
    const float v1 = r1 * em;
    const float v2 = r2 * em;

    float* outb = out + (size_t)b * 3 * HW_;
    float* wgtb = g_weight + (size_t)b * HW_;

    #pragma unroll
    for (int cy = 0; cy < 2; cy++) {
        const int yi = qy0 + cy;
        if (yi < 0 || yi >= H_) continue;
        const float wyc = cy ? uy : (1.f - uy);
        #pragma unroll
        for (int cx = 0; cx < 2; cx++) {
            const int xi = qx0 + cx;
            if (xi < 0 || xi >= W_) continue;
            const float wt = wyc * (cx ? ux : (1.f - ux));
            const int idx = yi * W_ + xi;
            atomicAdd(outb + idx,            v0 * wt);
            atomicAdd(outb + HW_ + idx,      v1 * wt);
            atomicAdd(outb + 2 * HW_ + idx,  v2 * wt);
            atomicAdd(wgtb + idx,            em * wt);
        }
    }
}

// ---------------------------------------------------------------------------
// Kernel 3: normalize splat by weight + eps (in place on d_out).
// ---------------------------------------------------------------------------
__global__ void normalize_kernel(float* __restrict__ out) {
    int i = blockIdx.x * blockDim.x + threadIdx.x;
    if (i >= NPIX_) return;
    const int b  = i / HW_;
    const int hw = i - b * HW_;
    const float inv = 1.f / (g_weight[i] + 1e-7f);
    float* outb = out + (size_t)b * 3 * HW_;
    outb[hw]           *= inv;
    outb[HW_ + hw]     *= inv;
    outb[2 * HW_ + hw] *= inv;
}

extern "C" void kernel_launch(void* const* d_in, const int* in_sizes, int n_in,
                              void* d_out, int out_size) {
    const float* rgb1     = (const float*)d_in[0];
    const float* rgb2     = (const float*)d_in[1];
    const float* flow_tgt = (const float*)d_in[2];
    const float* flow12   = (const float*)d_in[3];

    float* out        = (float*)d_out;              // [B,3,H,W] splat_img
    float* metric_out = (float*)d_out + 3 * NPIX_;  // [B,1,H,W] metric

    // 1) zero accumulators
    {
        const int n = (3 * NPIX_) / 4;  // larger of the two float4 ranges
        const int threads = 256;
        zero_kernel<<<(n + threads - 1) / threads, threads>>>((float4*)out);
    }

    // 2) main fused kernel
    {
        const int threads = 256;
        const int blocks = (NPIX_ + threads - 1) / threads;
        softsplat_kernel<<<blocks, threads>>>(rgb1, rgb2, flow_tgt, flow12,
                                              out, metric_out);
    }

    // 3) normalize
    {
        const int threads = 256;
        const int blocks = (NPIX_ + threads - 1) / threads;
        normalize_kernel<<<blocks, threads>>>(out);
    }
}

// round 4
// speedup vs baseline: 2.0480x; 2.0480x over previous
#include <cuda_runtime.h>
#include <math.h>

// Problem shape (fixed by reference setup_inputs)
#define B_ 4
#define C_ 3
#define H_ 1024
#define W_ 1920
#define HW_ (H_ * W_)          // 1,966,080
#define NPIX_ (B_ * HW_)       // 7,864,320

// Interleaved splat accumulator: per pixel {r, g, b, em}. 16B aligned slots so
// one red.global.add.v4.f32 per bilinear corner. Static device scratch.
__device__ float4 g_acc[NPIX_];

// Vector atomic reduce: one instruction, 16 bytes, sm_90+.
__device__ __forceinline__ void red_add_v4(float4* addr, float a, float b,
                                           float c, float d) {
    asm volatile("red.global.add.v4.f32 [%0], {%1, %2, %3, %4};"
                 :: "l"(addr), "f"(a), "f"(b), "f"(c), "f"(d)
                 : "memory");
}

// ---------------------------------------------------------------------------
// Kernel 1: zero the interleaved accumulator (d_out needs no zeroing; the
// normalize kernel overwrites it fully).
// ---------------------------------------------------------------------------
__global__ void zero_kernel() {
    int i = blockIdx.x * blockDim.x + threadIdx.x;
    if (i < NPIX_) g_acc[i] = make_float4(0.f, 0.f, 0.f, 0.f);
}

// ---------------------------------------------------------------------------
// Kernel 2: per source pixel — backwarp rgb2, metric, exp weight, splat.
// ---------------------------------------------------------------------------
__global__ void __launch_bounds__(256)
softsplat_kernel(const float* __restrict__ rgb1,
                 const float* __restrict__ rgb2,
                 const float* __restrict__ flow_tgt,
                 const float* __restrict__ flow12,
                 float* __restrict__ metric_out) // [B,1,H,W]
{
    int i = blockIdx.x * blockDim.x + threadIdx.x;
    if (i >= NPIX_) return;

    const int b  = i / HW_;
    const int hw = i - b * HW_;
    const int h  = hw / W_;
    const int w  = hw - h * W_;

    // ---- backwarp rgb2 with flow_src1_to_src2 (bilinear, zero padding) ----
    const float* f12 = flow12 + (size_t)b * 2 * HW_;
    const float px = (float)w + f12[hw];
    const float py = (float)h + f12[HW_ + hw];
    const float x0f = floorf(px);
    const float y0f = floorf(py);
    const int   x0  = (int)x0f;
    const int   y0  = (int)y0f;
    const float wx  = px - x0f;
    const float wy  = py - y0f;

    const float* img2 = rgb2 + (size_t)b * 3 * HW_;
    float w00 = 0.f, w01 = 0.f, w02 = 0.f;  // warped channels

    if (x0 >= 0 && x0 < W_ && y0 >= 0 && y0 < H_) {
        const float wt = (1.f - wx) * (1.f - wy);
        const int idx = y0 * W_ + x0;
        w00 += __ldg(img2 + idx) * wt;
        w01 += __ldg(img2 + HW_ + idx) * wt;
        w02 += __ldg(img2 + 2 * HW_ + idx) * wt;
    }
    if (x0 + 1 >= 0 && x0 + 1 < W_ && y0 >= 0 && y0 < H_) {
        const float wt = wx * (1.f - wy);
        const int idx = y0 * W_ + x0 + 1;
        w00 += __ldg(img2 + idx) * wt;
        w01 += __ldg(img2 + HW_ + idx) * wt;
        w02 += __ldg(img2 + 2 * HW_ + idx) * wt;
    }
    if (x0 >= 0 && x0 < W_ && y0 + 1 >= 0 && y0 + 1 < H_) {
        const float wt = (1.f - wx) * wy;
        const int idx = (y0 + 1) * W_ + x0;
        w00 += __ldg(img2 + idx) * wt;
        w01 += __ldg(img2 + HW_ + idx) * wt;
        w02 += __ldg(img2 + 2 * HW_ + idx) * wt;
    }
    if (x0 + 1 >= 0 && x0 + 1 < W_ && y0 + 1 >= 0 && y0 + 1 < H_) {
        const float wt = wx * wy;
        const int idx = (y0 + 1) * W_ + x0 + 1;
        w00 += __ldg(img2 + idx) * wt;
        w01 += __ldg(img2 + HW_ + idx) * wt;
        w02 += __ldg(img2 + 2 * HW_ + idx) * wt;
    }

    // ---- metric = channel-mean L1(rgb1, backwarped) ----
    const float* img1 = rgb1 + (size_t)b * 3 * HW_;
    const float r0 = img1[hw];
    const float r1 = img1[HW_ + hw];
    const float r2 = img1[2 * HW_ + hw];

    const float metric = (fabsf(r0 - w00) + fabsf(r1 - w01) + fabsf(r2 - w02))
                         * (1.f / 3.f);
    metric_out[(size_t)b * HW_ + hw] = metric;

    // em = exp(clip(-100*metric, -100, 100)); metric >= 0 so upper clip moot
    const float em = __expf(fmaxf(-100.f * metric, -100.f));

    // ---- forward splat of {r*em, em} with flow_src1_to_tgt ----
    const float* ftg = flow_tgt + (size_t)b * 2 * HW_;
    const float qx = (float)w + ftg[hw];
    const float qy = (float)h + ftg[HW_ + hw];
    const float qx0f = floorf(qx);
    const float qy0f = floorf(qy);
    const int   qx0  = (int)qx0f;
    const int   qy0  = (int)qy0f;
    const float ux   = qx - qx0f;
    const float uy   = qy - qy0f;

    const float v0 = r0 * em;
    const float v1 = r1 * em;
    const float v2 = r2 * em;

    float4* accb = g_acc + (size_t)b * HW_;

    #pragma unroll
    for (int cy = 0; cy < 2; cy++) {
        const int yi = qy0 + cy;
        if (yi < 0 || yi >= H_) continue;
        const float wyc = cy ? uy : (1.f - uy);
        #pragma unroll
        for (int cx = 0; cx < 2; cx++) {
            const int xi = qx0 + cx;
            if (xi < 0 || xi >= W_) continue;
            const float wt = wyc * (cx ? ux : (1.f - ux));
            red_add_v4(accb + yi * W_ + xi, v0 * wt, v1 * wt, v2 * wt, em * wt);
        }
    }
}

// ---------------------------------------------------------------------------
// Kernel 3: normalize — read interleaved accumulator, write planar d_out.
// ---------------------------------------------------------------------------
__global__ void normalize_kernel(float* __restrict__ out) {
    int i = blockIdx.x * blockDim.x + threadIdx.x;
    if (i >= NPIX_) return;
    const int b  = i / HW_;
    const int hw = i - b * HW_;
    const float4 a = g_acc[i];
    const float inv = 1.f / (a.w + 1e-7f);
    float* outb = out + (size_t)b * 3 * HW_;
    outb[hw]           = a.x * inv;
    outb[HW_ + hw]     = a.y * inv;
    outb[2 * HW_ + hw] = a.z * inv;
}

extern "C" void kernel_launch(void* const* d_in, const int* in_sizes, int n_in,
                              void* d_out, int out_size) {
    const float* rgb1     = (const float*)d_in[0];
    const float* rgb2     = (const float*)d_in[1];
    const float* flow_tgt = (const float*)d_in[2];
    const float* flow12   = (const float*)d_in[3];

    float* out        = (float*)d_out;              // [B,3,H,W] splat_img
    float* metric_out = (float*)d_out + 3 * NPIX_;  // [B,1,H,W] metric

    const int threads = 256;
    const int blocks = (NPIX_ + threads - 1) / threads;

    zero_kernel<<<blocks, threads>>>();
    softsplat_kernel<<<blocks, threads>>>(rgb1, rgb2, flow_tgt, flow12,
                                          metric_out);
    normalize_kernel<<<blocks, threads>>>(out);
}

// round 5
// speedup vs baseline: 2.1607x; 1.0550x over previous
#include <cuda_runtime.h>
#include <math.h>

// Problem shape (fixed by reference setup_inputs)
#define B_ 4
#define C_ 3
#define H_ 1024
#define W_ 1920
#define HW_ (H_ * W_)          // 1,966,080
#define NPIX_ (B_ * HW_)       // 7,864,320

// Interleaved splat accumulator: per pixel {r, g, b, em}.
__device__ float4 g_acc[NPIX_];
// Interleaved copy of rgb2: per pixel {r, g, b, unused} so one 16B gather per
// bilinear corner instead of 3 scattered planar loads.
__device__ float4 g_rgb2x4[NPIX_];

// Vector atomic reduce: one instruction, 16 bytes, sm_90+.
__device__ __forceinline__ void red_add_v4(float4* addr, float a, float b,
                                           float c, float d) {
    asm volatile("red.global.add.v4.f32 [%0], {%1, %2, %3, %4};"
                 :: "l"(addr), "f"(a), "f"(b), "f"(c), "f"(d)
                 : "memory");
}

// ---------------------------------------------------------------------------
// Kernel 1: zero the accumulator AND build the interleaved rgb2 copy.
// All accesses fully coalesced (planar reads, float4 writes).
// ---------------------------------------------------------------------------
__global__ void __launch_bounds__(256)
prep_kernel(const float* __restrict__ rgb2) {
    int i = blockIdx.x * blockDim.x + threadIdx.x;
    if (i >= NPIX_) return;
    g_acc[i] = make_float4(0.f, 0.f, 0.f, 0.f);

    const int b  = i / HW_;
    const int hw = i - b * HW_;
    const float* img2 = rgb2 + (size_t)b * 3 * HW_;
    g_rgb2x4[i] = make_float4(img2[hw], img2[HW_ + hw], img2[2 * HW_ + hw], 0.f);
}

// ---------------------------------------------------------------------------
// Kernel 2: per source pixel — backwarp rgb2 (interleaved gather), metric,
// exp weight, vector-atomic splat.
// ---------------------------------------------------------------------------
__global__ void __launch_bounds__(256)
softsplat_kernel(const float* __restrict__ rgb1,
                 const float* __restrict__ flow_tgt,
                 const float* __restrict__ flow12,
                 float* __restrict__ metric_out) // [B,1,H,W]
{
    int i = blockIdx.x * blockDim.x + threadIdx.x;
    if (i >= NPIX_) return;

    const int b  = i / HW_;
    const int hw = i - b * HW_;
    const int h  = hw / W_;
    const int w  = hw - h * W_;

    // ---- backwarp rgb2 with flow_src1_to_src2 (bilinear, zero padding) ----
    const float* f12 = flow12 + (size_t)b * 2 * HW_;
    const float px = (float)w + f12[hw];
    const float py = (float)h + f12[HW_ + hw];
    const float x0f = floorf(px);
    const float y0f = floorf(py);
    const int   x0  = (int)x0f;
    const int   y0  = (int)y0f;
    const float wx  = px - x0f;
    const float wy  = py - y0f;

    const float4* img2 = g_rgb2x4 + (size_t)b * HW_;
    float w00 = 0.f, w01 = 0.f, w02 = 0.f;  // warped channels

    const bool xin0 = (x0 >= 0) & (x0 < W_);
    const bool xin1 = (x0 + 1 >= 0) & (x0 + 1 < W_);
    const bool yin0 = (y0 >= 0) & (y0 < H_);
    const bool yin1 = (y0 + 1 >= 0) & (y0 + 1 < H_);

    if (xin0 & yin0) {
        const float wt = (1.f - wx) * (1.f - wy);
        const float4 p = __ldg(img2 + y0 * W_ + x0);
        w00 += p.x * wt; w01 += p.y * wt; w02 += p.z * wt;
    }
    if (xin1 & yin0) {
        const float wt = wx * (1.f - wy);
        const float4 p = __ldg(img2 + y0 * W_ + x0 + 1);
        w00 += p.x * wt; w01 += p.y * wt; w02 += p.z * wt;
    }
    if (xin0 & yin1) {
        const float wt = (1.f - wx) * wy;
        const float4 p = __ldg(img2 + (y0 + 1) * W_ + x0);
        w00 += p.x * wt; w01 += p.y * wt; w02 += p.z * wt;
    }
    if (xin1 & yin1) {
        const float wt = wx * wy;
        const float4 p = __ldg(img2 + (y0 + 1) * W_ + x0 + 1);
        w00 += p.x * wt; w01 += p.y * wt; w02 += p.z * wt;
    }

    // ---- metric = channel-mean L1(rgb1, backwarped) ----
    const float* img1 = rgb1 + (size_t)b * 3 * HW_;
    const float r0 = img1[hw];
    const float r1 = img1[HW_ + hw];
    const float r2 = img1[2 * HW_ + hw];

    const float metric = (fabsf(r0 - w00) + fabsf(r1 - w01) + fabsf(r2 - w02))
                         * (1.f / 3.f);
    metric_out[(size_t)b * HW_ + hw] = metric;

    // em = exp(clip(-100*metric, -100, 100)); metric >= 0 so upper clip moot
    const float em = __expf(fmaxf(-100.f * metric, -100.f));

    // ---- forward splat of {r*em, em} with flow_src1_to_tgt ----
    const float* ftg = flow_tgt + (size_t)b * 2 * HW_;
    const float qx = (float)w + ftg[hw];
    const float qy = (float)h + ftg[HW_ + hw];
    const float qx0f = floorf(qx);
    const float qy0f = floorf(qy);
    const int   qx0  = (int)qx0f;
    const int   qy0  = (int)qy0f;
    const float ux   = qx - qx0f;
    const float uy   = qy - qy0f;

    const float v0 = r0 * em;
    const float v1 = r1 * em;
    const float v2 = r2 * em;

    float4* accb = g_acc + (size_t)b * HW_;

    #pragma unroll
    for (int cy = 0; cy < 2; cy++) {
        const int yi = qy0 + cy;
        if (yi < 0 || yi >= H_) continue;
        const float wyc = cy ? uy : (1.f - uy);
        #pragma unroll
        for (int cx = 0; cx < 2; cx++) {
            const int xi = qx0 + cx;
            if (xi < 0 || xi >= W_) continue;
            const float wt = wyc * (cx ? ux : (1.f - ux));
            red_add_v4(accb + yi * W_ + xi, v0 * wt, v1 * wt, v2 * wt, em * wt);
        }
    }
}

// ---------------------------------------------------------------------------
// Kernel 3: normalize — read interleaved accumulator, write planar d_out.
// ---------------------------------------------------------------------------
__global__ void __launch_bounds__(256)
normalize_kernel(float* __restrict__ out) {
    int i = blockIdx.x * blockDim.x + threadIdx.x;
    if (i >= NPIX_) return;
    const int b  = i / HW_;
    const int hw = i - b * HW_;
    const float4 a = g_acc[i];
    const float inv = 1.f / (a.w + 1e-7f);
    float* outb = out + (size_t)b * 3 * HW_;
    outb[hw]           = a.x * inv;
    outb[HW_ + hw]     = a.y * inv;
    outb[2 * HW_ + hw] = a.z * inv;
}

extern "C" void kernel_launch(void* const* d_in, const int* in_sizes, int n_in,
                              void* d_out, int out_size) {
    const float* rgb1     = (const float*)d_in[0];
    const float* rgb2     = (const float*)d_in[1];
    const float* flow_tgt = (const float*)d_in[2];
    const float* flow12   = (const float*)d_in[3];

    float* out        = (float*)d_out;              // [B,3,H,W] splat_img
    float* metric_out = (float*)d_out + 3 * NPIX_;  // [B,1,H,W] metric

    const int threads = 256;
    const int blocks = (NPIX_ + threads - 1) / threads;

    prep_kernel<<<blocks, threads>>>(rgb2);
    softsplat_kernel<<<blocks, threads>>>(rgb1, flow_tgt, flow12, metric_out);
    normalize_kernel<<<blocks, threads>>>(out);
}